// round 1
// baseline (speedup 1.0000x reference)
#include <cuda_runtime.h>
#include <cuda_bf16.h>
#include <math.h>

// ---------------------------------------------------------------------------
// Problem constants
// ---------------------------------------------------------------------------
#define NN   50000      // nodes
#define NE   1600000    // edges
#define HID  128
#define NG   500        // graphs
#define SLOPE 0.3f
#define BN_EPS 1e-5f

// ---------------------------------------------------------------------------
// Device scratch (no allocation allowed)
// ---------------------------------------------------------------------------
__device__ float g_xl[NN * HID];
__device__ float g_xr[NN * HID];
__device__ float g_h1[NN * HID];
__device__ float g_h2[NN * HID];
__device__ float g_gt[NN * HID];
__device__ int   g_deg[NN];
__device__ int   g_cursor[NN];
__device__ int   g_rowstart[NN + 1];
__device__ int   g_csr_src[NE];
__device__ float g_score[NN];
__device__ float g_wgt[NN];
__device__ unsigned int g_gmax[NG];
__device__ float g_gsum[NG];
__device__ float g_pooled[NG * HID];

// ---------------------------------------------------------------------------
// Small helpers
// ---------------------------------------------------------------------------
__global__ void zero32_kernel(unsigned int* p, int n) {
    int i = blockIdx.x * blockDim.x + threadIdx.x;
    if (i < n) p[i] = 0u;
}

__global__ void count_deg_kernel(const int* __restrict__ dst, int* __restrict__ deg, int e) {
    int i = blockIdx.x * blockDim.x + threadIdx.x;
    if (i < e) atomicAdd(&deg[dst[i]], 1);
}

// single-block inclusive scan -> rowstart
__global__ void scan_kernel(const int* __restrict__ deg, int* __restrict__ rowstart, int n) {
    __shared__ int buf[1024];
    __shared__ int s_base;
    int t = threadIdx.x;
    if (t == 0) { s_base = 0; rowstart[0] = 0; }
    __syncthreads();
    for (int start = 0; start < n; start += 1024) {
        int i = start + t;
        int v = (i < n) ? deg[i] : 0;
        buf[t] = v;
        __syncthreads();
        for (int off = 1; off < 1024; off <<= 1) {
            int add = (t >= off) ? buf[t - off] : 0;
            __syncthreads();
            buf[t] += add;
            __syncthreads();
        }
        int incl = buf[t];
        int base = s_base;
        if (i < n) rowstart[i + 1] = base + incl;
        __syncthreads();
        if (t == 1023) s_base = base + incl;
        __syncthreads();
    }
}

__global__ void fill_csr_kernel(const int* __restrict__ src, const int* __restrict__ dst,
                                const int* __restrict__ rowstart, int* __restrict__ cursor,
                                int* __restrict__ csr_src, int e) {
    int i = blockIdx.x * blockDim.x + threadIdx.x;
    if (i < e) {
        int d = dst[i];
        int pos = atomicAdd(&cursor[d], 1);
        csr_src[rowstart[d] + pos] = src[i];
    }
}

// ---------------------------------------------------------------------------
// GEMM: C[N,128] = A[N,128] @ W[128,128]   (+ optional tanh(v + bias) epilogue)
// 128x128 block tile, 8x8 thread micro-tile, 256 threads.
// ---------------------------------------------------------------------------
#define GKC 16
__global__ __launch_bounds__(256) void gemm128_kernel(
        const float* __restrict__ A, const float* __restrict__ W,
        const float* __restrict__ bias, float* __restrict__ C,
        int n, int op /*0: none, 1: tanh(v+bias)*/) {
    __shared__ float As[GKC][132];
    __shared__ float Bs[GKC][128];
    int tid = threadIdx.x;
    int tx = tid & 15, ty = tid >> 4;
    int rowBase = blockIdx.x * 128;
    int r0 = ty * 8, c0 = tx * 8;

    float acc[8][8];
#pragma unroll
    for (int i = 0; i < 8; i++)
#pragma unroll
        for (int j = 0; j < 8; j++) acc[i][j] = 0.f;

    for (int k0 = 0; k0 < 128; k0 += GKC) {
#pragma unroll
        for (int it = 0; it < 2; it++) {
            int i = tid + it * 256;      // 0..511
            int r = i >> 2;              // 0..127
            int kq = i & 3;              // 0..3
            int grow = rowBase + r;
            float4 v = make_float4(0.f, 0.f, 0.f, 0.f);
            if (grow < n) v = *(const float4*)(A + (size_t)grow * 128 + k0 + kq * 4);
            As[kq * 4 + 0][r] = v.x;
            As[kq * 4 + 1][r] = v.y;
            As[kq * 4 + 2][r] = v.z;
            As[kq * 4 + 3][r] = v.w;
        }
#pragma unroll
        for (int it = 0; it < 2; it++) {
            int i = tid + it * 256;
            int k = i >> 5;              // 0..15
            int c4 = i & 31;             // 0..31
            float4 v = *(const float4*)(W + (size_t)(k0 + k) * 128 + c4 * 4);
            *(float4*)&Bs[k][c4 * 4] = v;
        }
        __syncthreads();
#pragma unroll
        for (int k = 0; k < GKC; k++) {
            float a[8], b[8];
#pragma unroll
            for (int i = 0; i < 8; i++) a[i] = As[k][r0 + i];
#pragma unroll
            for (int j = 0; j < 8; j++) b[j] = Bs[k][c0 + j];
#pragma unroll
            for (int i = 0; i < 8; i++)
#pragma unroll
                for (int j = 0; j < 8; j++) acc[i][j] = fmaf(a[i], b[j], acc[i][j]);
        }
        __syncthreads();
    }

#pragma unroll
    for (int i = 0; i < 8; i++) {
        int row = rowBase + r0 + i;
        if (row >= n) break;
#pragma unroll
        for (int j = 0; j < 8; j++) {
            float v = acc[i][j];
            int c = c0 + j;
            if (op == 1) v = tanhf(v + bias[c]);
            C[(size_t)row * 128 + c] = v;
        }
    }
}

// ---------------------------------------------------------------------------
// GATv2 aggregation: one warp per destination node, online softmax.
// GROUP = lanes per attention head group (4 for 8 heads x 16ch, 32 for 1 head)
// ---------------------------------------------------------------------------
template <int GROUP>
__device__ __forceinline__ float group_reduce(float v) {
    v += __shfl_xor_sync(0xffffffffu, v, 1);
    v += __shfl_xor_sync(0xffffffffu, v, 2);
    if (GROUP == 32) {
        v += __shfl_xor_sync(0xffffffffu, v, 4);
        v += __shfl_xor_sync(0xffffffffu, v, 8);
        v += __shfl_xor_sync(0xffffffffu, v, 16);
    }
    return v;
}

__device__ __forceinline__ float lrelu(float x) { return x > 0.f ? x : x * SLOPE; }

template <int GROUP>
__global__ __launch_bounds__(256) void gat_agg_kernel(
        const float* __restrict__ xl, const float* __restrict__ xr,
        const float* __restrict__ att, const float* __restrict__ bias,
        const float* __restrict__ bn_g, const float* __restrict__ bn_b,
        const float* __restrict__ bn_rm, const float* __restrict__ bn_rv,
        const int* __restrict__ rowstart, const int* __restrict__ csr_src,
        float* __restrict__ out, int n) {
    int w = (blockIdx.x * blockDim.x + threadIdx.x) >> 5;
    if (w >= n) return;
    int lane = threadIdx.x & 31;
    int j = lane * 4;

    float4 r4 = *(const float4*)(xr + (size_t)w * 128 + j);
    float4 a4 = *(const float4*)(att + j);

    int e0 = rowstart[w], e1 = rowstart[w + 1];
    float m = -INFINITY, s = 0.f;
    float4 acc = make_float4(0.f, 0.f, 0.f, 0.f);

    auto upd = [&](float4 lv) {
        float sc = lrelu(lv.x + r4.x) * a4.x + lrelu(lv.y + r4.y) * a4.y +
                   lrelu(lv.z + r4.z) * a4.z + lrelu(lv.w + r4.w) * a4.w;
        sc = group_reduce<GROUP>(sc);
        float mn = fmaxf(m, sc);
        float scale = __expf(m - mn);
        float p = __expf(sc - mn);
        s = s * scale + p;
        acc.x = fmaf(p, lv.x, acc.x * scale);
        acc.y = fmaf(p, lv.y, acc.y * scale);
        acc.z = fmaf(p, lv.z, acc.z * scale);
        acc.w = fmaf(p, lv.w, acc.w * scale);
        m = mn;
    };

    int e = e0;
#pragma unroll 1
    for (; e + 1 < e1; e += 2) {
        int sa = csr_src[e];
        int sb = csr_src[e + 1];
        float4 la = *(const float4*)(xl + (size_t)sa * 128 + j);
        float4 lb = *(const float4*)(xl + (size_t)sb * 128 + j);
        upd(la);
        upd(lb);
    }
    if (e < e1) {
        int sa = csr_src[e];
        float4 la = *(const float4*)(xl + (size_t)sa * 128 + j);
        upd(la);
    }

    float inv = 1.0f / (s + 1e-16f);
    float4 bi = *(const float4*)(bias + j);
    float4 gg = *(const float4*)(bn_g + j);
    float4 bb = *(const float4*)(bn_b + j);
    float4 rm = *(const float4*)(bn_rm + j);
    float4 rv = *(const float4*)(bn_rv + j);

    float4 o;
    o.x = acc.x * inv + bi.x;
    o.y = acc.y * inv + bi.y;
    o.z = acc.z * inv + bi.z;
    o.w = acc.w * inv + bi.w;
    o.x = fmaxf(0.f, (o.x - rm.x) * (gg.x * rsqrtf(rv.x + BN_EPS)) + bb.x);
    o.y = fmaxf(0.f, (o.y - rm.y) * (gg.y * rsqrtf(rv.y + BN_EPS)) + bb.y);
    o.z = fmaxf(0.f, (o.z - rm.z) * (gg.z * rsqrtf(rv.z + BN_EPS)) + bb.z);
    o.w = fmaxf(0.f, (o.w - rm.w) * (gg.w * rsqrtf(rv.w + BN_EPS)) + bb.w);
    *(float4*)(out + (size_t)w * 128 + j) = o;
}

// ---------------------------------------------------------------------------
// Attentional aggregation (segment softmax over graphs)
// ---------------------------------------------------------------------------
__device__ __forceinline__ unsigned int ford(float f) {
    unsigned int u = __float_as_uint(f);
    return (u & 0x80000000u) ? ~u : (u | 0x80000000u);
}
__device__ __forceinline__ float forddec(unsigned int u) {
    return (u & 0x80000000u) ? __uint_as_float(u & 0x7fffffffu) : __uint_as_float(~u);
}

__global__ __launch_bounds__(256) void gate_score_kernel(
        const float* __restrict__ gt, const float* __restrict__ Wg2,
        const int* __restrict__ batch, unsigned int* __restrict__ gmax,
        float* __restrict__ score, int n) {
    int w = (blockIdx.x * blockDim.x + threadIdx.x) >> 5;
    if (w >= n) return;
    int lane = threadIdx.x & 31;
    int j = lane * 4;
    float4 gv = *(const float4*)(gt + (size_t)w * 128 + j);
    float4 wg = *(const float4*)(Wg2 + j);
    float sc = gv.x * wg.x + gv.y * wg.y + gv.z * wg.z + gv.w * wg.w;
    sc = group_reduce<32>(sc);
    if (lane == 0) {
        score[w] = sc;
        atomicMax(&gmax[batch[w]], ford(sc));
    }
}

__global__ void gate_expsum_kernel(const float* __restrict__ score,
                                   const int* __restrict__ batch,
                                   const unsigned int* __restrict__ gmax,
                                   float* __restrict__ wgt, float* __restrict__ gsum, int n) {
    int i = blockIdx.x * blockDim.x + threadIdx.x;
    if (i < n) {
        int g = batch[i];
        float mx = forddec(gmax[g]);
        float wv = __expf(score[i] - mx);
        wgt[i] = wv;
        atomicAdd(&gsum[g], wv);
    }
}

__global__ __launch_bounds__(256) void pool_kernel(
        const float* __restrict__ h2, const float* __restrict__ wgt,
        const float* __restrict__ gsum, const int* __restrict__ batch,
        float* __restrict__ pooled, int n) {
    int w = (blockIdx.x * blockDim.x + threadIdx.x) >> 5;
    if (w >= n) return;
    int lane = threadIdx.x & 31;
    int j = lane * 4;
    int g = batch[w];
    float coef = wgt[w] / (gsum[g] + 1e-16f);
    float4 h = *(const float4*)(h2 + (size_t)w * 128 + j);
    float* base = pooled + (size_t)g * 128 + j;
    atomicAdd(base + 0, coef * h.x);
    atomicAdd(base + 1, coef * h.y);
    atomicAdd(base + 2, coef * h.z);
    atomicAdd(base + 3, coef * h.w);
}

// ---------------------------------------------------------------------------
// fc head: relu(pooled @ Wf1 + bf1) @ Wf2 + bf2   -> out[g]
// one block (128 thr) per graph
// ---------------------------------------------------------------------------
__global__ __launch_bounds__(128) void fc_head_kernel(
        const float* __restrict__ pooled,
        const float* __restrict__ Wf1, const float* __restrict__ bf1,
        const float* __restrict__ Wf2, const float* __restrict__ bf2,
        float* __restrict__ out) {
    int g = blockIdx.x;
    int t = threadIdx.x;
    __shared__ float sp[128];
    __shared__ float red[128];
    sp[t] = pooled[(size_t)g * 128 + t];
    __syncthreads();
    float contrib = 0.f;
    if (t < 100) {
        float acc = bf1[t];
#pragma unroll 8
        for (int k = 0; k < 128; k++) acc = fmaf(sp[k], Wf1[k * 100 + t], acc);
        contrib = fmaxf(acc, 0.f) * Wf2[t];
    }
    red[t] = contrib;
    __syncthreads();
    for (int off = 64; off > 0; off >>= 1) {
        if (t < off) red[t] += red[t + off];
        __syncthreads();
    }
    if (t == 0) out[g] = red[0] + bf2[0];
}

// ---------------------------------------------------------------------------
// Host driver
// ---------------------------------------------------------------------------
extern "C" void kernel_launch(void* const* d_in, const int* in_sizes, int n_in,
                              void* d_out, int out_size) {
    const float* x    = (const float*)d_in[0];
    const int*   ei   = (const int*)d_in[1];
    const int*   batch= (const int*)d_in[2];
    const float* Wl1  = (const float*)d_in[3];
    const float* Wr1  = (const float*)d_in[4];
    const float* att1 = (const float*)d_in[5];
    const float* b1   = (const float*)d_in[6];
    const float* Wl2  = (const float*)d_in[7];
    const float* Wr2  = (const float*)d_in[8];
    const float* att2 = (const float*)d_in[9];
    const float* b2   = (const float*)d_in[10];
    const float* bn_g = (const float*)d_in[11];
    const float* bn_b = (const float*)d_in[12];
    const float* bn_rm= (const float*)d_in[13];
    const float* bn_rv= (const float*)d_in[14];
    const float* Wg1  = (const float*)d_in[15];
    const float* bg1  = (const float*)d_in[16];
    const float* Wg2  = (const float*)d_in[17];
    const float* Wf1  = (const float*)d_in[18];
    const float* bf1  = (const float*)d_in[19];
    const float* Wf2  = (const float*)d_in[20];
    const float* bf2  = (const float*)d_in[21];

    const int n = in_sizes[0] / HID;      // 50000
    const int e = in_sizes[1] / 2;        // 1600000
    const int ng = out_size;              // 500
    const int* src = ei;
    const int* dst = ei + e;

    // scratch pointers
    float *xl, *xr, *h1, *h2, *gt, *score, *wgt, *gsum, *pooled;
    int *deg, *cursor, *rowstart, *csr_src;
    unsigned int* gmax;
    cudaGetSymbolAddress((void**)&xl, g_xl);
    cudaGetSymbolAddress((void**)&xr, g_xr);
    cudaGetSymbolAddress((void**)&h1, g_h1);
    cudaGetSymbolAddress((void**)&h2, g_h2);
    cudaGetSymbolAddress((void**)&gt, g_gt);
    cudaGetSymbolAddress((void**)&deg, g_deg);
    cudaGetSymbolAddress((void**)&cursor, g_cursor);
    cudaGetSymbolAddress((void**)&rowstart, g_rowstart);
    cudaGetSymbolAddress((void**)&csr_src, g_csr_src);
    cudaGetSymbolAddress((void**)&score, g_score);
    cudaGetSymbolAddress((void**)&wgt, g_wgt);
    cudaGetSymbolAddress((void**)&gmax, g_gmax);
    cudaGetSymbolAddress((void**)&gsum, g_gsum);
    cudaGetSymbolAddress((void**)&pooled, g_pooled);

    const int TB = 256;
    int gemmGrid = (n + 127) / 128;
    int warpGrid = (n * 32 + TB - 1) / TB;

    // ---- CSR build ----
    zero32_kernel<<<(n + TB - 1) / TB, TB>>>((unsigned int*)deg, n);
    zero32_kernel<<<(n + TB - 1) / TB, TB>>>((unsigned int*)cursor, n);
    count_deg_kernel<<<(e + TB - 1) / TB, TB>>>(dst, deg, e);
    scan_kernel<<<1, 1024>>>(deg, rowstart, n);
    fill_csr_kernel<<<(e + TB - 1) / TB, TB>>>(src, dst, rowstart, cursor, csr_src, e);

    // ---- layer 1 ----
    gemm128_kernel<<<gemmGrid, 256>>>(x, Wl1, nullptr, xl, n, 0);
    gemm128_kernel<<<gemmGrid, 256>>>(x, Wr1, nullptr, xr, n, 0);
    gat_agg_kernel<4><<<warpGrid, TB>>>(xl, xr, att1, b1, bn_g, bn_b, bn_rm, bn_rv,
                                        rowstart, csr_src, h1, n);

    // ---- layer 2 ----
    gemm128_kernel<<<gemmGrid, 256>>>(h1, Wl2, nullptr, xl, n, 0);
    gemm128_kernel<<<gemmGrid, 256>>>(h1, Wr2, nullptr, xr, n, 0);
    gat_agg_kernel<32><<<warpGrid, TB>>>(xl, xr, att2, b2, bn_g, bn_b, bn_rm, bn_rv,
                                         rowstart, csr_src, h2, n);

    // ---- attentional aggregation ----
    gemm128_kernel<<<gemmGrid, 256>>>(h2, Wg1, bg1, gt, n, 1);  // tanh(h2@Wg1 + bg1)
    zero32_kernel<<<(ng + TB - 1) / TB, TB>>>(gmax, ng);
    zero32_kernel<<<(ng + TB - 1) / TB, TB>>>((unsigned int*)gsum, ng);
    zero32_kernel<<<(ng * HID + TB - 1) / TB, TB>>>((unsigned int*)pooled, ng * HID);
    gate_score_kernel<<<warpGrid, TB>>>(gt, Wg2, batch, gmax, score, n);
    gate_expsum_kernel<<<(n + TB - 1) / TB, TB>>>(score, batch, gmax, wgt, gsum, n);
    pool_kernel<<<warpGrid, TB>>>(h2, wgt, gsum, batch, pooled, n);

    // ---- fc head ----
    fc_head_kernel<<<ng, 128>>>(pooled, Wf1, bf1, Wf2, bf2, (float*)d_out);
}

// round 2
// speedup vs baseline: 1.1414x; 1.1414x over previous
#include <cuda_runtime.h>
#include <cuda_bf16.h>
#include <math.h>

// ---------------------------------------------------------------------------
// Problem constants
// ---------------------------------------------------------------------------
#define NN   50000      // nodes
#define NE   1600000    // edges
#define HID  128
#define NG   500        // graphs
#define SLOPE 0.3f
#define BN_EPS 1e-5f

// ---------------------------------------------------------------------------
// Device scratch (no allocation allowed)
// ---------------------------------------------------------------------------
__device__ float g_xl[NN * HID];
__device__ float g_xr[NN * HID];
__device__ float g_h1[NN * HID];
__device__ float g_h2[NN * HID];
__device__ float g_gt[NN * HID];
__device__ int   g_deg[NN];
__device__ int   g_cursor[NN];
__device__ int   g_rowstart[NN + 1];
__device__ int   g_bsums[64];
__device__ int   g_csr_src[NE];
__device__ float g_score[NN];
__device__ float g_wgt[NN];
__device__ unsigned int g_gmax[NG];
__device__ float g_gsum[NG];
__device__ float g_pooled[NG * HID];

// ---------------------------------------------------------------------------
// CSR build helpers
// ---------------------------------------------------------------------------
__global__ void count_deg_kernel(const int* __restrict__ dst, int* __restrict__ deg, int e) {
    int i = blockIdx.x * blockDim.x + threadIdx.x;
    if (i < e) atomicAdd(&deg[dst[i]], 1);
}

// phase 1: per-block inclusive scan (block = 1024 elements)
__global__ __launch_bounds__(1024) void scan_block_kernel(
        const int* __restrict__ deg, int* __restrict__ rowstart,
        int* __restrict__ bsums, int n) {
    __shared__ int buf[1024];
    int t = threadIdx.x;
    int i = blockIdx.x * 1024 + t;
    int v = (i < n) ? deg[i] : 0;
    buf[t] = v;
    __syncthreads();
#pragma unroll
    for (int off = 1; off < 1024; off <<= 1) {
        int add = (t >= off) ? buf[t - off] : 0;
        __syncthreads();
        buf[t] += add;
        __syncthreads();
    }
    if (i < n) rowstart[i + 1] = buf[t];
    if (t == 1023) bsums[blockIdx.x] = buf[1023];
    if (i == 0) rowstart[0] = 0;
}

// phase 2: scan the (<=64) block sums in one small block
__global__ __launch_bounds__(64) void scan_sums_kernel(int* __restrict__ bsums, int nb) {
    __shared__ int buf[64];
    int t = threadIdx.x;
    buf[t] = (t < nb) ? bsums[t] : 0;
    __syncthreads();
#pragma unroll
    for (int off = 1; off < 64; off <<= 1) {
        int add = (t >= off) ? buf[t - off] : 0;
        __syncthreads();
        buf[t] += add;
        __syncthreads();
    }
    if (t < nb) bsums[t] = buf[t];
}

// phase 3: add exclusive block offsets
__global__ void scan_add_kernel(int* __restrict__ rowstart, const int* __restrict__ bsums, int n) {
    int i = blockIdx.x * blockDim.x + threadIdx.x;
    if (i < n) {
        int b = i >> 10;
        if (b > 0) rowstart[i + 1] += bsums[b - 1];
    }
}

__global__ void fill_csr_kernel(const int* __restrict__ src, const int* __restrict__ dst,
                                const int* __restrict__ rowstart, int* __restrict__ cursor,
                                int* __restrict__ csr_src, int e) {
    int i = blockIdx.x * blockDim.x + threadIdx.x;
    if (i < e) {
        int d = dst[i];
        int pos = atomicAdd(&cursor[d], 1);
        csr_src[rowstart[d] + pos] = src[i];
    }
}

// ---------------------------------------------------------------------------
// GEMM: C[N,128] = A[N,128] @ W[128,128]   (+ optional tanh(v + bias) epilogue)
// 128x128 block tile, 8x8 thread micro-tile, 256 threads.
// ---------------------------------------------------------------------------
#define GKC 16
__global__ __launch_bounds__(256) void gemm128_kernel(
        const float* __restrict__ A, const float* __restrict__ W,
        const float* __restrict__ bias, float* __restrict__ C,
        int n, int op /*0: none, 1: tanh(v+bias)*/) {
    __shared__ float As[GKC][132];
    __shared__ float Bs[GKC][128];
    int tid = threadIdx.x;
    int tx = tid & 15, ty = tid >> 4;
    int rowBase = blockIdx.x * 128;
    int r0 = ty * 8, c0 = tx * 8;

    float acc[8][8];
#pragma unroll
    for (int i = 0; i < 8; i++)
#pragma unroll
        for (int j = 0; j < 8; j++) acc[i][j] = 0.f;

    for (int k0 = 0; k0 < 128; k0 += GKC) {
#pragma unroll
        for (int it = 0; it < 2; it++) {
            int i = tid + it * 256;      // 0..511
            int r = i >> 2;              // 0..127
            int kq = i & 3;              // 0..3
            int grow = rowBase + r;
            float4 v = make_float4(0.f, 0.f, 0.f, 0.f);
            if (grow < n) v = *(const float4*)(A + (size_t)grow * 128 + k0 + kq * 4);
            As[kq * 4 + 0][r] = v.x;
            As[kq * 4 + 1][r] = v.y;
            As[kq * 4 + 2][r] = v.z;
            As[kq * 4 + 3][r] = v.w;
        }
#pragma unroll
        for (int it = 0; it < 2; it++) {
            int i = tid + it * 256;
            int k = i >> 5;              // 0..15
            int c4 = i & 31;             // 0..31
            float4 v = *(const float4*)(W + (size_t)(k0 + k) * 128 + c4 * 4);
            *(float4*)&Bs[k][c4 * 4] = v;
        }
        __syncthreads();
#pragma unroll
        for (int k = 0; k < GKC; k++) {
            float a[8], b[8];
#pragma unroll
            for (int i = 0; i < 8; i++) a[i] = As[k][r0 + i];
#pragma unroll
            for (int j = 0; j < 8; j++) b[j] = Bs[k][c0 + j];
#pragma unroll
            for (int i = 0; i < 8; i++)
#pragma unroll
                for (int j = 0; j < 8; j++) acc[i][j] = fmaf(a[i], b[j], acc[i][j]);
        }
        __syncthreads();
    }

#pragma unroll
    for (int i = 0; i < 8; i++) {
        int row = rowBase + r0 + i;
        if (row >= n) break;
#pragma unroll
        for (int j = 0; j < 8; j++) {
            float v = acc[i][j];
            int c = c0 + j;
            if (op == 1) v = tanhf(v + bias[c]);
            C[(size_t)row * 128 + c] = v;
        }
    }
}

// ---------------------------------------------------------------------------
// GATv2 aggregation: one warp per destination node, online softmax, batch-4.
// GROUP = lanes per attention head group (4 for 8 heads x 16ch, 32 for 1 head)
// ---------------------------------------------------------------------------
template <int GROUP>
__device__ __forceinline__ float group_reduce(float v) {
    v += __shfl_xor_sync(0xffffffffu, v, 1);
    v += __shfl_xor_sync(0xffffffffu, v, 2);
    if (GROUP == 32) {
        v += __shfl_xor_sync(0xffffffffu, v, 4);
        v += __shfl_xor_sync(0xffffffffu, v, 8);
        v += __shfl_xor_sync(0xffffffffu, v, 16);
    }
    return v;
}

__device__ __forceinline__ float lrelu(float x) { return x > 0.f ? x : x * SLOPE; }

template <int GROUP>
__global__ __launch_bounds__(256) void gat_agg_kernel(
        const float* __restrict__ xl, const float* __restrict__ xr,
        const float* __restrict__ att, const float* __restrict__ bias,
        const float* __restrict__ bn_g, const float* __restrict__ bn_b,
        const float* __restrict__ bn_rm, const float* __restrict__ bn_rv,
        const int* __restrict__ rowstart, const int* __restrict__ csr_src,
        float* __restrict__ out, int n) {
    int w = (blockIdx.x * blockDim.x + threadIdx.x) >> 5;
    if (w >= n) return;
    int lane = threadIdx.x & 31;
    int j = lane * 4;

    float4 r4 = *(const float4*)(xr + (size_t)w * 128 + j);
    float4 a4 = *(const float4*)(att + j);

    int e0 = rowstart[w], e1 = rowstart[w + 1];
    float m = -INFINITY, s = 0.f;
    float4 acc = make_float4(0.f, 0.f, 0.f, 0.f);

    auto score_of = [&](const float4& lv) {
        float sc = lrelu(lv.x + r4.x) * a4.x + lrelu(lv.y + r4.y) * a4.y +
                   lrelu(lv.z + r4.z) * a4.z + lrelu(lv.w + r4.w) * a4.w;
        return group_reduce<GROUP>(sc);
    };

    int e = e0;
#pragma unroll 1
    for (; e + 3 < e1; e += 4) {
        // 4 independent gathers -> MLP=4
        int s0 = csr_src[e + 0], s1 = csr_src[e + 1];
        int s2 = csr_src[e + 2], s3 = csr_src[e + 3];
        float4 l0 = *(const float4*)(xl + (size_t)s0 * 128 + j);
        float4 l1 = *(const float4*)(xl + (size_t)s1 * 128 + j);
        float4 l2 = *(const float4*)(xl + (size_t)s2 * 128 + j);
        float4 l3 = *(const float4*)(xl + (size_t)s3 * 128 + j);
        float sc0 = score_of(l0), sc1 = score_of(l1);
        float sc2 = score_of(l2), sc3 = score_of(l3);
        // single combined online-softmax update for the batch of 4
        float mn = fmaxf(m, fmaxf(fmaxf(sc0, sc1), fmaxf(sc2, sc3)));
        float scale = __expf(m - mn);
        float p0 = __expf(sc0 - mn), p1 = __expf(sc1 - mn);
        float p2 = __expf(sc2 - mn), p3 = __expf(sc3 - mn);
        s = fmaf(s, scale, p0 + p1 + p2 + p3);
        acc.x = fmaf(acc.x, scale, fmaf(p0, l0.x, fmaf(p1, l1.x, fmaf(p2, l2.x, p3 * l3.x))));
        acc.y = fmaf(acc.y, scale, fmaf(p0, l0.y, fmaf(p1, l1.y, fmaf(p2, l2.y, p3 * l3.y))));
        acc.z = fmaf(acc.z, scale, fmaf(p0, l0.z, fmaf(p1, l1.z, fmaf(p2, l2.z, p3 * l3.z))));
        acc.w = fmaf(acc.w, scale, fmaf(p0, l0.w, fmaf(p1, l1.w, fmaf(p2, l2.w, p3 * l3.w))));
        m = mn;
    }
#pragma unroll 1
    for (; e < e1; e++) {
        int sa = csr_src[e];
        float4 lv = *(const float4*)(xl + (size_t)sa * 128 + j);
        float sc = score_of(lv);
        float mn = fmaxf(m, sc);
        float scale = __expf(m - mn);
        float p = __expf(sc - mn);
        s = fmaf(s, scale, p);
        acc.x = fmaf(acc.x, scale, p * lv.x);
        acc.y = fmaf(acc.y, scale, p * lv.y);
        acc.z = fmaf(acc.z, scale, p * lv.z);
        acc.w = fmaf(acc.w, scale, p * lv.w);
        m = mn;
    }

    float inv = 1.0f / (s + 1e-16f);
    float4 bi = *(const float4*)(bias + j);
    float4 gg = *(const float4*)(bn_g + j);
    float4 bb = *(const float4*)(bn_b + j);
    float4 rm = *(const float4*)(bn_rm + j);
    float4 rv = *(const float4*)(bn_rv + j);

    float4 o;
    o.x = acc.x * inv + bi.x;
    o.y = acc.y * inv + bi.y;
    o.z = acc.z * inv + bi.z;
    o.w = acc.w * inv + bi.w;
    o.x = fmaxf(0.f, (o.x - rm.x) * (gg.x * rsqrtf(rv.x + BN_EPS)) + bb.x);
    o.y = fmaxf(0.f, (o.y - rm.y) * (gg.y * rsqrtf(rv.y + BN_EPS)) + bb.y);
    o.z = fmaxf(0.f, (o.z - rm.z) * (gg.z * rsqrtf(rv.z + BN_EPS)) + bb.z);
    o.w = fmaxf(0.f, (o.w - rm.w) * (gg.w * rsqrtf(rv.w + BN_EPS)) + bb.w);
    *(float4*)(out + (size_t)w * 128 + j) = o;
}

// ---------------------------------------------------------------------------
// Attentional aggregation (segment softmax over graphs)
// ---------------------------------------------------------------------------
__device__ __forceinline__ unsigned int ford(float f) {
    unsigned int u = __float_as_uint(f);
    return (u & 0x80000000u) ? ~u : (u | 0x80000000u);
}
__device__ __forceinline__ float forddec(unsigned int u) {
    return (u & 0x80000000u) ? __uint_as_float(u & 0x7fffffffu) : __uint_as_float(~u);
}

__global__ __launch_bounds__(256) void gate_score_kernel(
        const float* __restrict__ gt, const float* __restrict__ Wg2,
        const int* __restrict__ batch, unsigned int* __restrict__ gmax,
        float* __restrict__ score, int n) {
    int w = (blockIdx.x * blockDim.x + threadIdx.x) >> 5;
    if (w >= n) return;
    int lane = threadIdx.x & 31;
    int j = lane * 4;
    float4 gv = *(const float4*)(gt + (size_t)w * 128 + j);
    float4 wg = *(const float4*)(Wg2 + j);
    float sc = gv.x * wg.x + gv.y * wg.y + gv.z * wg.z + gv.w * wg.w;
    sc = group_reduce<32>(sc);
    if (lane == 0) {
        score[w] = sc;
        atomicMax(&gmax[batch[w]], ford(sc));
    }
}

__global__ void gate_expsum_kernel(const float* __restrict__ score,
                                   const int* __restrict__ batch,
                                   const unsigned int* __restrict__ gmax,
                                   float* __restrict__ wgt, float* __restrict__ gsum, int n) {
    int i = blockIdx.x * blockDim.x + threadIdx.x;
    if (i < n) {
        int g = batch[i];
        float mx = forddec(gmax[g]);
        float wv = __expf(score[i] - mx);
        wgt[i] = wv;
        atomicAdd(&gsum[g], wv);
    }
}

__global__ __launch_bounds__(256) void pool_kernel(
        const float* __restrict__ h2, const float* __restrict__ wgt,
        const float* __restrict__ gsum, const int* __restrict__ batch,
        float* __restrict__ pooled, int n) {
    int w = (blockIdx.x * blockDim.x + threadIdx.x) >> 5;
    if (w >= n) return;
    int lane = threadIdx.x & 31;
    int j = lane * 4;
    int g = batch[w];
    float coef = wgt[w] / (gsum[g] + 1e-16f);
    float4 h = *(const float4*)(h2 + (size_t)w * 128 + j);
    float* base = pooled + (size_t)g * 128 + j;
    atomicAdd(base + 0, coef * h.x);
    atomicAdd(base + 1, coef * h.y);
    atomicAdd(base + 2, coef * h.z);
    atomicAdd(base + 3, coef * h.w);
}

// ---------------------------------------------------------------------------
// fc head: relu(pooled @ Wf1 + bf1) @ Wf2 + bf2   -> out[g]
// one block (128 thr) per graph
// ---------------------------------------------------------------------------
__global__ __launch_bounds__(128) void fc_head_kernel(
        const float* __restrict__ pooled,
        const float* __restrict__ Wf1, const float* __restrict__ bf1,
        const float* __restrict__ Wf2, const float* __restrict__ bf2,
        float* __restrict__ out) {
    int g = blockIdx.x;
    int t = threadIdx.x;
    __shared__ float sp[128];
    __shared__ float red[128];
    sp[t] = pooled[(size_t)g * 128 + t];
    __syncthreads();
    float contrib = 0.f;
    if (t < 100) {
        float acc = bf1[t];
#pragma unroll 8
        for (int k = 0; k < 128; k++) acc = fmaf(sp[k], Wf1[k * 100 + t], acc);
        contrib = fmaxf(acc, 0.f) * Wf2[t];
    }
    red[t] = contrib;
    __syncthreads();
    for (int off = 64; off > 0; off >>= 1) {
        if (t < off) red[t] += red[t + off];
        __syncthreads();
    }
    if (t == 0) out[g] = red[0] + bf2[0];
}

// ---------------------------------------------------------------------------
// Host driver
// ---------------------------------------------------------------------------
extern "C" void kernel_launch(void* const* d_in, const int* in_sizes, int n_in,
                              void* d_out, int out_size) {
    const float* x    = (const float*)d_in[0];
    const int*   ei   = (const int*)d_in[1];
    const int*   batch= (const int*)d_in[2];
    const float* Wl1  = (const float*)d_in[3];
    const float* Wr1  = (const float*)d_in[4];
    const float* att1 = (const float*)d_in[5];
    const float* b1   = (const float*)d_in[6];
    const float* Wl2  = (const float*)d_in[7];
    const float* Wr2  = (const float*)d_in[8];
    const float* att2 = (const float*)d_in[9];
    const float* b2   = (const float*)d_in[10];
    const float* bn_g = (const float*)d_in[11];
    const float* bn_b = (const float*)d_in[12];
    const float* bn_rm= (const float*)d_in[13];
    const float* bn_rv= (const float*)d_in[14];
    const float* Wg1  = (const float*)d_in[15];
    const float* bg1  = (const float*)d_in[16];
    const float* Wg2  = (const float*)d_in[17];
    const float* Wf1  = (const float*)d_in[18];
    const float* bf1  = (const float*)d_in[19];
    const float* Wf2  = (const float*)d_in[20];
    const float* bf2  = (const float*)d_in[21];

    const int n = in_sizes[0] / HID;      // 50000
    const int e = in_sizes[1] / 2;        // 1600000
    const int ng = out_size;              // 500
    const int* src = ei;
    const int* dst = ei + e;

    // scratch pointers
    float *xl, *xr, *h1, *h2, *gt, *score, *wgt, *gsum, *pooled;
    int *deg, *cursor, *rowstart, *csr_src, *bsums;
    unsigned int* gmax;
    cudaGetSymbolAddress((void**)&xl, g_xl);
    cudaGetSymbolAddress((void**)&xr, g_xr);
    cudaGetSymbolAddress((void**)&h1, g_h1);
    cudaGetSymbolAddress((void**)&h2, g_h2);
    cudaGetSymbolAddress((void**)&gt, g_gt);
    cudaGetSymbolAddress((void**)&deg, g_deg);
    cudaGetSymbolAddress((void**)&cursor, g_cursor);
    cudaGetSymbolAddress((void**)&rowstart, g_rowstart);
    cudaGetSymbolAddress((void**)&bsums, g_bsums);
    cudaGetSymbolAddress((void**)&csr_src, g_csr_src);
    cudaGetSymbolAddress((void**)&score, g_score);
    cudaGetSymbolAddress((void**)&wgt, g_wgt);
    cudaGetSymbolAddress((void**)&gmax, g_gmax);
    cudaGetSymbolAddress((void**)&gsum, g_gsum);
    cudaGetSymbolAddress((void**)&pooled, g_pooled);

    const int TB = 256;
    int gemmGrid = (n + 127) / 128;
    int warpGrid = (n * 32 + TB - 1) / TB;
    int nScanBlocks = (n + 1023) / 1024;

    // ---- CSR build ----
    cudaMemsetAsync(deg, 0, n * sizeof(int));
    cudaMemsetAsync(cursor, 0, n * sizeof(int));
    count_deg_kernel<<<(e + TB - 1) / TB, TB>>>(dst, deg, e);
    scan_block_kernel<<<nScanBlocks, 1024>>>(deg, rowstart, bsums, n);
    scan_sums_kernel<<<1, 64>>>(bsums, nScanBlocks);
    scan_add_kernel<<<(n + TB - 1) / TB, TB>>>(rowstart, bsums, n);
    fill_csr_kernel<<<(e + TB - 1) / TB, TB>>>(src, dst, rowstart, cursor, csr_src, e);

    // ---- layer 1 ----
    gemm128_kernel<<<gemmGrid, 256>>>(x, Wl1, nullptr, xl, n, 0);
    gemm128_kernel<<<gemmGrid, 256>>>(x, Wr1, nullptr, xr, n, 0);
    gat_agg_kernel<4><<<warpGrid, TB>>>(xl, xr, att1, b1, bn_g, bn_b, bn_rm, bn_rv,
                                        rowstart, csr_src, h1, n);

    // ---- layer 2 ----
    gemm128_kernel<<<gemmGrid, 256>>>(h1, Wl2, nullptr, xl, n, 0);
    gemm128_kernel<<<gemmGrid, 256>>>(h1, Wr2, nullptr, xr, n, 0);
    gat_agg_kernel<32><<<warpGrid, TB>>>(xl, xr, att2, b2, bn_g, bn_b, bn_rm, bn_rv,
                                         rowstart, csr_src, h2, n);

    // ---- attentional aggregation ----
    gemm128_kernel<<<gemmGrid, 256>>>(h2, Wg1, bg1, gt, n, 1);  // tanh(h2@Wg1 + bg1)
    cudaMemsetAsync(gmax, 0, ng * sizeof(unsigned int));
    cudaMemsetAsync(gsum, 0, ng * sizeof(float));
    cudaMemsetAsync(pooled, 0, ng * HID * sizeof(float));
    gate_score_kernel<<<warpGrid, TB>>>(gt, Wg2, batch, gmax, score, n);
    gate_expsum_kernel<<<(n + TB - 1) / TB, TB>>>(score, batch, gmax, wgt, gsum, n);
    pool_kernel<<<warpGrid, TB>>>(h2, wgt, gsum, batch, pooled, n);

    // ---- fc head ----
    fc_head_kernel<<<ng, 128>>>(pooled, Wf1, bf1, Wf2, bf2, (float*)d_out);
}

// round 3
// speedup vs baseline: 1.7676x; 1.5486x over previous
#include <cuda_runtime.h>
#include <cuda_bf16.h>
#include <math.h>

// ---------------------------------------------------------------------------
// Problem constants
// ---------------------------------------------------------------------------
#define NN   50000      // nodes
#define NE   1600000    // edges
#define HID  128
#define NG   500        // graphs
#define SLOPE 0.3f
#define BN_EPS 1e-5f

// ---------------------------------------------------------------------------
// Device scratch (no allocation allowed)
// ---------------------------------------------------------------------------
__device__ float g_xl[NN * HID];
__device__ float g_xr[NN * HID];
__device__ float g_h1[NN * HID];
__device__ float g_h2[NN * HID];
__device__ int   g_deg[NN];
__device__ int   g_cursor[NN];
__device__ int   g_rowstart[NN + 1];
__device__ int   g_bsums[64];
__device__ int   g_csr_src[NE];
__device__ float g_score[NN];
__device__ float g_wgt[NN];
__device__ unsigned int g_gmax[NG];
__device__ float g_gsum[NG];
__device__ float g_pooled[NG * HID];

// ---------------------------------------------------------------------------
// Order-preserving float<->uint for atomicMax on floats
// ---------------------------------------------------------------------------
__device__ __forceinline__ unsigned int ford(float f) {
    unsigned int u = __float_as_uint(f);
    return (u & 0x80000000u) ? ~u : (u | 0x80000000u);
}
__device__ __forceinline__ float forddec(unsigned int u) {
    return (u & 0x80000000u) ? __uint_as_float(u & 0x7fffffffu) : __uint_as_float(~u);
}

// ---------------------------------------------------------------------------
// CSR build helpers
// ---------------------------------------------------------------------------
__global__ void count_deg_kernel(const int* __restrict__ dst, int* __restrict__ deg, int e) {
    int i = blockIdx.x * blockDim.x + threadIdx.x;
    if (i < e) atomicAdd(&deg[dst[i]], 1);
}

__global__ __launch_bounds__(1024) void scan_block_kernel(
        const int* __restrict__ deg, int* __restrict__ rowstart,
        int* __restrict__ bsums, int n) {
    __shared__ int buf[1024];
    int t = threadIdx.x;
    int i = blockIdx.x * 1024 + t;
    int v = (i < n) ? deg[i] : 0;
    buf[t] = v;
    __syncthreads();
#pragma unroll
    for (int off = 1; off < 1024; off <<= 1) {
        int add = (t >= off) ? buf[t - off] : 0;
        __syncthreads();
        buf[t] += add;
        __syncthreads();
    }
    if (i < n) rowstart[i + 1] = buf[t];
    if (t == 1023) bsums[blockIdx.x] = buf[1023];
    if (i == 0) rowstart[0] = 0;
}

__global__ __launch_bounds__(64) void scan_sums_kernel(int* __restrict__ bsums, int nb) {
    __shared__ int buf[64];
    int t = threadIdx.x;
    buf[t] = (t < nb) ? bsums[t] : 0;
    __syncthreads();
#pragma unroll
    for (int off = 1; off < 64; off <<= 1) {
        int add = (t >= off) ? buf[t - off] : 0;
        __syncthreads();
        buf[t] += add;
        __syncthreads();
    }
    if (t < nb) bsums[t] = buf[t];
}

__global__ void scan_add_kernel(int* __restrict__ rowstart, const int* __restrict__ bsums, int n) {
    int i = blockIdx.x * blockDim.x + threadIdx.x;
    if (i < n) {
        int b = i >> 10;
        if (b > 0) rowstart[i + 1] += bsums[b - 1];
    }
}

__global__ void fill_csr_kernel(const int* __restrict__ src, const int* __restrict__ dst,
                                const int* __restrict__ rowstart, int* __restrict__ cursor,
                                int* __restrict__ csr_src, int e) {
    int i = blockIdx.x * blockDim.x + threadIdx.x;
    if (i < e) {
        int d = dst[i];
        int pos = atomicAdd(&cursor[d], 1);
        csr_src[rowstart[d] + pos] = src[i];
    }
}

// ---------------------------------------------------------------------------
// TF32 tensor-core GEMM: C[N,128] = A[N,128] @ W[128,128]
// op 0: plain store to C
// op 2: gate epilogue: sc[row] = sum_c tanh(v+bias[c]) * Wg2[c];
//       writes score[row], atomicMax gmax[batch[row]]   (C not written)
// 128x128 block tile, 8 warps (each 32x64), K-chunk 32.
// ---------------------------------------------------------------------------
__device__ __forceinline__ unsigned int tf32cvt(float f) {
    unsigned int u;
    asm("cvt.rna.tf32.f32 %0, %1;" : "=r"(u) : "f"(f));
    return u;
}

__device__ __forceinline__ void mma16n8k8(float4& d, const unsigned int a[4],
                                          unsigned int b0, unsigned int b1) {
    asm volatile(
        "mma.sync.aligned.m16n8k8.row.col.f32.tf32.tf32.f32 "
        "{%0,%1,%2,%3}, {%4,%5,%6,%7}, {%8,%9}, {%0,%1,%2,%3};"
        : "+f"(d.x), "+f"(d.y), "+f"(d.z), "+f"(d.w)
        : "r"(a[0]), "r"(a[1]), "r"(a[2]), "r"(a[3]), "r"(b0), "r"(b1));
}

#define ASTRIDE 36
#define BSTRIDE 136

__global__ __launch_bounds__(256) void gemm_tf32_kernel(
        const float* __restrict__ A, const float* __restrict__ W,
        const float* __restrict__ bias, float* __restrict__ C,
        const int* __restrict__ batchv, const float* __restrict__ Wg2,
        unsigned int* __restrict__ gmax, float* __restrict__ score,
        int n, int op) {
    __shared__ float As[128 * ASTRIDE];   // 18.0 KB, bank-conflict-free frag loads
    __shared__ float Bs[32 * BSTRIDE];    // 17.4 KB
    __shared__ float sscore[128];

    int tid = threadIdx.x;
    int wid = tid >> 5, lane = tid & 31;
    int g = lane >> 2, tg = lane & 3;
    int warpM = (wid >> 1) * 32;   // 0,32,64,96
    int warpN = (wid & 1) * 64;    // 0,64
    int rowBase = blockIdx.x * 128;

    if (op == 2 && tid < 128) sscore[tid] = 0.f;

    float4 acc[2][8];
#pragma unroll
    for (int mt = 0; mt < 2; mt++)
#pragma unroll
        for (int nt = 0; nt < 8; nt++) acc[mt][nt] = make_float4(0.f, 0.f, 0.f, 0.f);

    for (int k0 = 0; k0 < 128; k0 += 32) {
        // stage A tile [128 rows x 32 k], tf32-rounded
#pragma unroll
        for (int it = 0; it < 4; it++) {
            int idx = tid + it * 256;          // 0..1023 float4 slots
            int row = idx >> 3, k4 = idx & 7;
            int grow = rowBase + row;
            float4 v = make_float4(0.f, 0.f, 0.f, 0.f);
            if (grow < n) v = *(const float4*)(A + (size_t)grow * 128 + k0 + k4 * 4);
            float4 t;
            t.x = __uint_as_float(tf32cvt(v.x));
            t.y = __uint_as_float(tf32cvt(v.y));
            t.z = __uint_as_float(tf32cvt(v.z));
            t.w = __uint_as_float(tf32cvt(v.w));
            *(float4*)&As[row * ASTRIDE + k4 * 4] = t;
        }
        // stage B tile [32 k x 128 n], tf32-rounded
#pragma unroll
        for (int it = 0; it < 4; it++) {
            int idx = tid + it * 256;          // 0..1023 float4 slots
            int k = idx >> 5, n4 = idx & 31;
            float4 v = *(const float4*)(W + (size_t)(k0 + k) * 128 + n4 * 4);
            float4 t;
            t.x = __uint_as_float(tf32cvt(v.x));
            t.y = __uint_as_float(tf32cvt(v.y));
            t.z = __uint_as_float(tf32cvt(v.z));
            t.w = __uint_as_float(tf32cvt(v.w));
            *(float4*)&Bs[k * BSTRIDE + n4 * 4] = t;
        }
        __syncthreads();

#pragma unroll
        for (int kk = 0; kk < 4; kk++) {
            unsigned int bfr[8][2];
#pragma unroll
            for (int nt = 0; nt < 8; nt++) {
                int col = warpN + nt * 8 + g;
                bfr[nt][0] = __float_as_uint(Bs[(kk * 8 + tg) * BSTRIDE + col]);
                bfr[nt][1] = __float_as_uint(Bs[(kk * 8 + tg + 4) * BSTRIDE + col]);
            }
#pragma unroll
            for (int mt = 0; mt < 2; mt++) {
                int r0 = warpM + mt * 16 + g;
                unsigned int a[4];
                a[0] = __float_as_uint(As[r0 * ASTRIDE + kk * 8 + tg]);
                a[1] = __float_as_uint(As[(r0 + 8) * ASTRIDE + kk * 8 + tg]);
                a[2] = __float_as_uint(As[r0 * ASTRIDE + kk * 8 + tg + 4]);
                a[3] = __float_as_uint(As[(r0 + 8) * ASTRIDE + kk * 8 + tg + 4]);
#pragma unroll
                for (int nt = 0; nt < 8; nt++)
                    mma16n8k8(acc[mt][nt], a, bfr[nt][0], bfr[nt][1]);
            }
        }
        __syncthreads();
    }

    if (op == 2) {
        // gate epilogue: per-row dot of tanh(v + bias) with Wg2
        float rp[2][2] = {{0.f, 0.f}, {0.f, 0.f}};
#pragma unroll
        for (int mt = 0; mt < 2; mt++) {
#pragma unroll
            for (int nt = 0; nt < 8; nt++) {
                int c0 = warpN + nt * 8 + tg * 2;
                float4 d = acc[mt][nt];
                float w0 = Wg2[c0], w1 = Wg2[c0 + 1];
                float b0 = bias[c0], b1 = bias[c0 + 1];
                rp[mt][0] += tanhf(d.x + b0) * w0 + tanhf(d.y + b1) * w1;
                rp[mt][1] += tanhf(d.z + b0) * w0 + tanhf(d.w + b1) * w1;
            }
            atomicAdd(&sscore[warpM + mt * 16 + g], rp[mt][0]);
            atomicAdd(&sscore[warpM + mt * 16 + g + 8], rp[mt][1]);
        }
        __syncthreads();
        if (tid < 128) {
            int row = rowBase + tid;
            if (row < n) {
                float sc = sscore[tid];
                score[row] = sc;
                atomicMax(&gmax[batchv[row]], ford(sc));
            }
        }
    } else {
#pragma unroll
        for (int mt = 0; mt < 2; mt++) {
#pragma unroll
            for (int nt = 0; nt < 8; nt++) {
                int c0 = warpN + nt * 8 + tg * 2;
                int r0 = rowBase + warpM + mt * 16 + g;
                float4 d = acc[mt][nt];
                if (r0 < n)     *(float2*)(C + (size_t)r0 * 128 + c0) = make_float2(d.x, d.y);
                if (r0 + 8 < n) *(float2*)(C + (size_t)(r0 + 8) * 128 + c0) = make_float2(d.z, d.w);
            }
        }
    }
}

// ---------------------------------------------------------------------------
// GATv2 aggregation: one warp per destination node, online softmax, batch-4.
// GROUP = lanes per attention head group (4 for 8 heads x 16ch, 32 for 1 head)
// ---------------------------------------------------------------------------
template <int GROUP>
__device__ __forceinline__ float group_reduce(float v) {
    v += __shfl_xor_sync(0xffffffffu, v, 1);
    v += __shfl_xor_sync(0xffffffffu, v, 2);
    if (GROUP == 32) {
        v += __shfl_xor_sync(0xffffffffu, v, 4);
        v += __shfl_xor_sync(0xffffffffu, v, 8);
        v += __shfl_xor_sync(0xffffffffu, v, 16);
    }
    return v;
}

__device__ __forceinline__ float lrelu(float x) { return x > 0.f ? x : x * SLOPE; }

template <int GROUP>
__global__ __launch_bounds__(256) void gat_agg_kernel(
        const float* __restrict__ xl, const float* __restrict__ xr,
        const float* __restrict__ att, const float* __restrict__ bias,
        const float* __restrict__ bn_g, const float* __restrict__ bn_b,
        const float* __restrict__ bn_rm, const float* __restrict__ bn_rv,
        const int* __restrict__ rowstart, const int* __restrict__ csr_src,
        float* __restrict__ out, int n) {
    int w = (blockIdx.x * blockDim.x + threadIdx.x) >> 5;
    if (w >= n) return;
    int lane = threadIdx.x & 31;
    int j = lane * 4;

    float4 r4 = *(const float4*)(xr + (size_t)w * 128 + j);
    float4 a4 = *(const float4*)(att + j);

    int e0 = rowstart[w], e1 = rowstart[w + 1];
    float m = -INFINITY, s = 0.f;
    float4 acc = make_float4(0.f, 0.f, 0.f, 0.f);

    auto score_of = [&](const float4& lv) {
        float sc = lrelu(lv.x + r4.x) * a4.x + lrelu(lv.y + r4.y) * a4.y +
                   lrelu(lv.z + r4.z) * a4.z + lrelu(lv.w + r4.w) * a4.w;
        return group_reduce<GROUP>(sc);
    };

    int e = e0;
#pragma unroll 1
    for (; e + 3 < e1; e += 4) {
        int s0 = csr_src[e + 0], s1 = csr_src[e + 1];
        int s2 = csr_src[e + 2], s3 = csr_src[e + 3];
        float4 l0 = *(const float4*)(xl + (size_t)s0 * 128 + j);
        float4 l1 = *(const float4*)(xl + (size_t)s1 * 128 + j);
        float4 l2 = *(const float4*)(xl + (size_t)s2 * 128 + j);
        float4 l3 = *(const float4*)(xl + (size_t)s3 * 128 + j);
        float sc0 = score_of(l0), sc1 = score_of(l1);
        float sc2 = score_of(l2), sc3 = score_of(l3);
        float mn = fmaxf(m, fmaxf(fmaxf(sc0, sc1), fmaxf(sc2, sc3)));
        float scale = __expf(m - mn);
        float p0 = __expf(sc0 - mn), p1 = __expf(sc1 - mn);
        float p2 = __expf(sc2 - mn), p3 = __expf(sc3 - mn);
        s = fmaf(s, scale, p0 + p1 + p2 + p3);
        acc.x = fmaf(acc.x, scale, fmaf(p0, l0.x, fmaf(p1, l1.x, fmaf(p2, l2.x, p3 * l3.x))));
        acc.y = fmaf(acc.y, scale, fmaf(p0, l0.y, fmaf(p1, l1.y, fmaf(p2, l2.y, p3 * l3.y))));
        acc.z = fmaf(acc.z, scale, fmaf(p0, l0.z, fmaf(p1, l1.z, fmaf(p2, l2.z, p3 * l3.z))));
        acc.w = fmaf(acc.w, scale, fmaf(p0, l0.w, fmaf(p1, l1.w, fmaf(p2, l2.w, p3 * l3.w))));
        m = mn;
    }
#pragma unroll 1
    for (; e < e1; e++) {
        int sa = csr_src[e];
        float4 lv = *(const float4*)(xl + (size_t)sa * 128 + j);
        float sc = score_of(lv);
        float mn = fmaxf(m, sc);
        float scale = __expf(m - mn);
        float p = __expf(sc - mn);
        s = fmaf(s, scale, p);
        acc.x = fmaf(acc.x, scale, p * lv.x);
        acc.y = fmaf(acc.y, scale, p * lv.y);
        acc.z = fmaf(acc.z, scale, p * lv.z);
        acc.w = fmaf(acc.w, scale, p * lv.w);
        m = mn;
    }

    float inv = 1.0f / (s + 1e-16f);
    float4 bi = *(const float4*)(bias + j);
    float4 gg = *(const float4*)(bn_g + j);
    float4 bb = *(const float4*)(bn_b + j);
    float4 rm = *(const float4*)(bn_rm + j);
    float4 rv = *(const float4*)(bn_rv + j);

    float4 o;
    o.x = acc.x * inv + bi.x;
    o.y = acc.y * inv + bi.y;
    o.z = acc.z * inv + bi.z;
    o.w = acc.w * inv + bi.w;
    o.x = fmaxf(0.f, (o.x - rm.x) * (gg.x * rsqrtf(rv.x + BN_EPS)) + bb.x);
    o.y = fmaxf(0.f, (o.y - rm.y) * (gg.y * rsqrtf(rv.y + BN_EPS)) + bb.y);
    o.z = fmaxf(0.f, (o.z - rm.z) * (gg.z * rsqrtf(rv.z + BN_EPS)) + bb.z);
    o.w = fmaxf(0.f, (o.w - rm.w) * (gg.w * rsqrtf(rv.w + BN_EPS)) + bb.w);
    *(float4*)(out + (size_t)w * 128 + j) = o;
}

// ---------------------------------------------------------------------------
// Attentional aggregation tail
// ---------------------------------------------------------------------------
__global__ void gate_expsum_kernel(const float* __restrict__ score,
                                   const int* __restrict__ batch,
                                   const unsigned int* __restrict__ gmax,
                                   float* __restrict__ wgt, float* __restrict__ gsum, int n) {
    int i = blockIdx.x * blockDim.x + threadIdx.x;
    if (i < n) {
        int g = batch[i];
        float mx = forddec(gmax[g]);
        float wv = __expf(score[i] - mx);
        wgt[i] = wv;
        atomicAdd(&gsum[g], wv);
    }
}

__global__ __launch_bounds__(256) void pool_kernel(
        const float* __restrict__ h2, const float* __restrict__ wgt,
        const float* __restrict__ gsum, const int* __restrict__ batch,
        float* __restrict__ pooled, int n) {
    int w = (blockIdx.x * blockDim.x + threadIdx.x) >> 5;
    if (w >= n) return;
    int lane = threadIdx.x & 31;
    int j = lane * 4;
    int g = batch[w];
    float coef = wgt[w] / (gsum[g] + 1e-16f);
    float4 h = *(const float4*)(h2 + (size_t)w * 128 + j);
    float* base = pooled + (size_t)g * 128 + j;
    atomicAdd(base + 0, coef * h.x);
    atomicAdd(base + 1, coef * h.y);
    atomicAdd(base + 2, coef * h.z);
    atomicAdd(base + 3, coef * h.w);
}

// ---------------------------------------------------------------------------
// fc head: relu(pooled @ Wf1 + bf1) @ Wf2 + bf2   -> out[g]
// ---------------------------------------------------------------------------
__global__ __launch_bounds__(128) void fc_head_kernel(
        const float* __restrict__ pooled,
        const float* __restrict__ Wf1, const float* __restrict__ bf1,
        const float* __restrict__ Wf2, const float* __restrict__ bf2,
        float* __restrict__ out) {
    int g = blockIdx.x;
    int t = threadIdx.x;
    __shared__ float sp[128];
    __shared__ float red[128];
    sp[t] = pooled[(size_t)g * 128 + t];
    __syncthreads();
    float contrib = 0.f;
    if (t < 100) {
        float acc = bf1[t];
#pragma unroll 8
        for (int k = 0; k < 128; k++) acc = fmaf(sp[k], Wf1[k * 100 + t], acc);
        contrib = fmaxf(acc, 0.f) * Wf2[t];
    }
    red[t] = contrib;
    __syncthreads();
    for (int off = 64; off > 0; off >>= 1) {
        if (t < off) red[t] += red[t + off];
        __syncthreads();
    }
    if (t == 0) out[g] = red[0] + bf2[0];
}

// ---------------------------------------------------------------------------
// Host driver
// ---------------------------------------------------------------------------
extern "C" void kernel_launch(void* const* d_in, const int* in_sizes, int n_in,
                              void* d_out, int out_size) {
    const float* x    = (const float*)d_in[0];
    const int*   ei   = (const int*)d_in[1];
    const int*   batch= (const int*)d_in[2];
    const float* Wl1  = (const float*)d_in[3];
    const float* Wr1  = (const float*)d_in[4];
    const float* att1 = (const float*)d_in[5];
    const float* b1   = (const float*)d_in[6];
    const float* Wl2  = (const float*)d_in[7];
    const float* Wr2  = (const float*)d_in[8];
    const float* att2 = (const float*)d_in[9];
    const float* b2   = (const float*)d_in[10];
    const float* bn_g = (const float*)d_in[11];
    const float* bn_b = (const float*)d_in[12];
    const float* bn_rm= (const float*)d_in[13];
    const float* bn_rv= (const float*)d_in[14];
    const float* Wg1  = (const float*)d_in[15];
    const float* bg1  = (const float*)d_in[16];
    const float* Wg2  = (const float*)d_in[17];
    const float* Wf1  = (const float*)d_in[18];
    const float* bf1  = (const float*)d_in[19];
    const float* Wf2  = (const float*)d_in[20];
    const float* bf2  = (const float*)d_in[21];

    const int n = in_sizes[0] / HID;      // 50000
    const int e = in_sizes[1] / 2;        // 1600000
    const int ng = out_size;              // 500
    const int* src = ei;
    const int* dst = ei + e;

    float *xl, *xr, *h1, *h2, *score, *wgt, *gsum, *pooled;
    int *deg, *cursor, *rowstart, *csr_src, *bsums;
    unsigned int* gmax;
    cudaGetSymbolAddress((void**)&xl, g_xl);
    cudaGetSymbolAddress((void**)&xr, g_xr);
    cudaGetSymbolAddress((void**)&h1, g_h1);
    cudaGetSymbolAddress((void**)&h2, g_h2);
    cudaGetSymbolAddress((void**)&deg, g_deg);
    cudaGetSymbolAddress((void**)&cursor, g_cursor);
    cudaGetSymbolAddress((void**)&rowstart, g_rowstart);
    cudaGetSymbolAddress((void**)&bsums, g_bsums);
    cudaGetSymbolAddress((void**)&csr_src, g_csr_src);
    cudaGetSymbolAddress((void**)&score, g_score);
    cudaGetSymbolAddress((void**)&wgt, g_wgt);
    cudaGetSymbolAddress((void**)&gmax, g_gmax);
    cudaGetSymbolAddress((void**)&gsum, g_gsum);
    cudaGetSymbolAddress((void**)&pooled, g_pooled);

    const int TB = 256;
    int gemmGrid = (n + 127) / 128;
    int warpGrid = (n * 32 + TB - 1) / TB;
    int nScanBlocks = (n + 1023) / 1024;

    // ---- CSR build ----
    cudaMemsetAsync(deg, 0, n * sizeof(int));
    cudaMemsetAsync(cursor, 0, n * sizeof(int));
    count_deg_kernel<<<(e + TB - 1) / TB, TB>>>(dst, deg, e);
    scan_block_kernel<<<nScanBlocks, 1024>>>(deg, rowstart, bsums, n);
    scan_sums_kernel<<<1, 64>>>(bsums, nScanBlocks);
    scan_add_kernel<<<(n + TB - 1) / TB, TB>>>(rowstart, bsums, n);
    fill_csr_kernel<<<(e + TB - 1) / TB, TB>>>(src, dst, rowstart, cursor, csr_src, e);

    // ---- layer 1 ----
    gemm_tf32_kernel<<<gemmGrid, 256>>>(x, Wl1, nullptr, xl, nullptr, nullptr, nullptr, nullptr, n, 0);
    gemm_tf32_kernel<<<gemmGrid, 256>>>(x, Wr1, nullptr, xr, nullptr, nullptr, nullptr, nullptr, n, 0);
    gat_agg_kernel<4><<<warpGrid, TB>>>(xl, xr, att1, b1, bn_g, bn_b, bn_rm, bn_rv,
                                        rowstart, csr_src, h1, n);

    // ---- layer 2 ----
    gemm_tf32_kernel<<<gemmGrid, 256>>>(h1, Wl2, nullptr, xl, nullptr, nullptr, nullptr, nullptr, n, 0);
    gemm_tf32_kernel<<<gemmGrid, 256>>>(h1, Wr2, nullptr, xr, nullptr, nullptr, nullptr, nullptr, n, 0);
    gat_agg_kernel<32><<<warpGrid, TB>>>(xl, xr, att2, b2, bn_g, bn_b, bn_rm, bn_rv,
                                         rowstart, csr_src, h2, n);

    // ---- attentional aggregation (gate fused into GEMM epilogue) ----
    cudaMemsetAsync(gmax, 0, ng * sizeof(unsigned int));
    cudaMemsetAsync(gsum, 0, ng * sizeof(float));
    cudaMemsetAsync(pooled, 0, ng * HID * sizeof(float));
    gemm_tf32_kernel<<<gemmGrid, 256>>>(h2, Wg1, bg1, nullptr, batch, Wg2, gmax, score, n, 2);
    gate_expsum_kernel<<<(n + TB - 1) / TB, TB>>>(score, batch, gmax, wgt, gsum, n);
    pool_kernel<<<warpGrid, TB>>>(h2, wgt, gsum, batch, pooled, n);

    // ---- fc head ----
    fc_head_kernel<<<ng, 128>>>(pooled, Wf1, bf1, Wf2, bf2, (float*)d_out);
}

// round 5
// speedup vs baseline: 1.7933x; 1.0146x over previous
#include <cuda_runtime.h>
#include <cuda_fp16.h>
#include <math.h>

// ---------------------------------------------------------------------------
// Problem constants
// ---------------------------------------------------------------------------
#define NN   50000      // nodes
#define NE   1600000    // edges
#define HID  128
#define NG   500        // graphs
#define SLOPE 0.3f
#define BN_EPS 1e-5f

// ---------------------------------------------------------------------------
// Device scratch (no allocation allowed)
// ---------------------------------------------------------------------------
__device__ __half g_xlh[NN * HID];     // fp16 message features (gather-heavy)
__device__ float  g_xr[NN * HID];
__device__ float  g_h1[NN * HID];
__device__ float  g_h2[NN * HID];
__device__ int    g_deg[NN];
__device__ int    g_cursor[NN];
__device__ int    g_rowstart[NN + 1];
__device__ int    g_bsums[64];
__device__ int    g_csr_src[NE];
__device__ float  g_score[NN];
__device__ unsigned int g_gmax[NG];
__device__ float  g_gsum[NG];
__device__ float  g_pooled[NG * HID];

// ---------------------------------------------------------------------------
// Order-preserving float<->uint for atomicMax on floats
// ---------------------------------------------------------------------------
__device__ __forceinline__ unsigned int ford(float f) {
    unsigned int u = __float_as_uint(f);
    return (u & 0x80000000u) ? ~u : (u | 0x80000000u);
}
__device__ __forceinline__ float forddec(unsigned int u) {
    return (u & 0x80000000u) ? __uint_as_float(u & 0x7fffffffu) : __uint_as_float(~u);
}

// ---------------------------------------------------------------------------
// CSR build helpers
// ---------------------------------------------------------------------------
__global__ void count_deg_kernel(const int* __restrict__ dst, int* __restrict__ deg, int e) {
    int i = blockIdx.x * blockDim.x + threadIdx.x;
    if (i < e) atomicAdd(&deg[dst[i]], 1);
}

__global__ __launch_bounds__(1024) void scan_block_kernel(
        const int* __restrict__ deg, int* __restrict__ rowstart,
        int* __restrict__ bsums, int n) {
    __shared__ int buf[1024];
    int t = threadIdx.x;
    int i = blockIdx.x * 1024 + t;
    int v = (i < n) ? deg[i] : 0;
    buf[t] = v;
    __syncthreads();
#pragma unroll
    for (int off = 1; off < 1024; off <<= 1) {
        int add = (t >= off) ? buf[t - off] : 0;
        __syncthreads();
        buf[t] += add;
        __syncthreads();
    }
    if (i < n) rowstart[i + 1] = buf[t];
    if (t == 1023) bsums[blockIdx.x] = buf[1023];
    if (i == 0) rowstart[0] = 0;
}

__global__ __launch_bounds__(64) void scan_sums_kernel(int* __restrict__ bsums, int nb) {
    __shared__ int buf[64];
    int t = threadIdx.x;
    buf[t] = (t < nb) ? bsums[t] : 0;
    __syncthreads();
#pragma unroll
    for (int off = 1; off < 64; off <<= 1) {
        int add = (t >= off) ? buf[t - off] : 0;
        __syncthreads();
        buf[t] += add;
        __syncthreads();
    }
    if (t < nb) bsums[t] = buf[t];
}

__global__ void scan_add_kernel(int* __restrict__ rowstart, const int* __restrict__ bsums, int n) {
    int i = blockIdx.x * blockDim.x + threadIdx.x;
    if (i < n) {
        int b = i >> 10;
        if (b > 0) rowstart[i + 1] += bsums[b - 1];
    }
}

__global__ void fill_csr_kernel(const int* __restrict__ src, const int* __restrict__ dst,
                                const int* __restrict__ rowstart, int* __restrict__ cursor,
                                int* __restrict__ csr_src, int e) {
    int i = blockIdx.x * blockDim.x + threadIdx.x;
    if (i < e) {
        int d = dst[i];
        int pos = atomicAdd(&cursor[d], 1);
        csr_src[rowstart[d] + pos] = src[i];
    }
}

// ---------------------------------------------------------------------------
// TF32 tensor-core GEMM: [N,128] @ [128,128]
// op 0: fp32 store to C
// op 1: fp16 store to Ch
// op 2: gate epilogue: score[row] = sum_c tanh(v+bias[c])*Wg2[c]; atomicMax gmax
// 128x128 block tile, 8 warps (each 32x64), K-chunk 32.
// ---------------------------------------------------------------------------
__device__ __forceinline__ unsigned int tf32cvt(float f) {
    unsigned int u;
    asm("cvt.rna.tf32.f32 %0, %1;" : "=r"(u) : "f"(f));
    return u;
}

__device__ __forceinline__ void mma16n8k8(float4& d, const unsigned int a[4],
                                          unsigned int b0, unsigned int b1) {
    asm volatile(
        "mma.sync.aligned.m16n8k8.row.col.f32.tf32.tf32.f32 "
        "{%0,%1,%2,%3}, {%4,%5,%6,%7}, {%8,%9}, {%0,%1,%2,%3};"
        : "+f"(d.x), "+f"(d.y), "+f"(d.z), "+f"(d.w)
        : "r"(a[0]), "r"(a[1]), "r"(a[2]), "r"(a[3]), "r"(b0), "r"(b1));
}

#define ASTRIDE 36
#define BSTRIDE 136

__global__ __launch_bounds__(256) void gemm_tf32_kernel(
        const float* __restrict__ A, const float* __restrict__ W,
        const float* __restrict__ bias, float* __restrict__ C,
        __half* __restrict__ Ch,
        const int* __restrict__ batchv, const float* __restrict__ Wg2,
        unsigned int* __restrict__ gmax, float* __restrict__ score,
        int n, int op) {
    __shared__ float As[128 * ASTRIDE];
    __shared__ float Bs[32 * BSTRIDE];
    __shared__ float sscore[128];

    int tid = threadIdx.x;
    int wid = tid >> 5, lane = tid & 31;
    int g = lane >> 2, tg = lane & 3;
    int warpM = (wid >> 1) * 32;   // 0,32,64,96
    int warpN = (wid & 1) * 64;    // 0,64
    int rowBase = blockIdx.x * 128;

    if (op == 2 && tid < 128) sscore[tid] = 0.f;

    float4 acc[2][8];
#pragma unroll
    for (int mt = 0; mt < 2; mt++)
#pragma unroll
        for (int nt = 0; nt < 8; nt++) acc[mt][nt] = make_float4(0.f, 0.f, 0.f, 0.f);

    for (int k0 = 0; k0 < 128; k0 += 32) {
#pragma unroll
        for (int it = 0; it < 4; it++) {
            int idx = tid + it * 256;
            int row = idx >> 3, k4 = idx & 7;
            int grow = rowBase + row;
            float4 v = make_float4(0.f, 0.f, 0.f, 0.f);
            if (grow < n) v = *(const float4*)(A + (size_t)grow * 128 + k0 + k4 * 4);
            float4 t;
            t.x = __uint_as_float(tf32cvt(v.x));
            t.y = __uint_as_float(tf32cvt(v.y));
            t.z = __uint_as_float(tf32cvt(v.z));
            t.w = __uint_as_float(tf32cvt(v.w));
            *(float4*)&As[row * ASTRIDE + k4 * 4] = t;
        }
#pragma unroll
        for (int it = 0; it < 4; it++) {
            int idx = tid + it * 256;
            int k = idx >> 5, n4 = idx & 31;
            float4 v = *(const float4*)(W + (size_t)(k0 + k) * 128 + n4 * 4);
            float4 t;
            t.x = __uint_as_float(tf32cvt(v.x));
            t.y = __uint_as_float(tf32cvt(v.y));
            t.z = __uint_as_float(tf32cvt(v.z));
            t.w = __uint_as_float(tf32cvt(v.w));
            *(float4*)&Bs[k * BSTRIDE + n4 * 4] = t;
        }
        __syncthreads();

#pragma unroll
        for (int kk = 0; kk < 4; kk++) {
            unsigned int bfr[8][2];
#pragma unroll
            for (int nt = 0; nt < 8; nt++) {
                int col = warpN + nt * 8 + g;
                bfr[nt][0] = __float_as_uint(Bs[(kk * 8 + tg) * BSTRIDE + col]);
                bfr[nt][1] = __float_as_uint(Bs[(kk * 8 + tg + 4) * BSTRIDE + col]);
            }
#pragma unroll
            for (int mt = 0; mt < 2; mt++) {
                int r0 = warpM + mt * 16 + g;
                unsigned int a[4];
                a[0] = __float_as_uint(As[r0 * ASTRIDE + kk * 8 + tg]);
                a[1] = __float_as_uint(As[(r0 + 8) * ASTRIDE + kk * 8 + tg]);
                a[2] = __float_as_uint(As[r0 * ASTRIDE + kk * 8 + tg + 4]);
                a[3] = __float_as_uint(As[(r0 + 8) * ASTRIDE + kk * 8 + tg + 4]);
#pragma unroll
                for (int nt = 0; nt < 8; nt++)
                    mma16n8k8(acc[mt][nt], a, bfr[nt][0], bfr[nt][1]);
            }
        }
        __syncthreads();
    }

    if (op == 2) {
        float rp[2][2] = {{0.f, 0.f}, {0.f, 0.f}};
#pragma unroll
        for (int mt = 0; mt < 2; mt++) {
#pragma unroll
            for (int nt = 0; nt < 8; nt++) {
                int c0 = warpN + nt * 8 + tg * 2;
                float4 d = acc[mt][nt];
                float w0 = Wg2[c0], w1 = Wg2[c0 + 1];
                float b0 = bias[c0], b1 = bias[c0 + 1];
                rp[mt][0] += tanhf(d.x + b0) * w0 + tanhf(d.y + b1) * w1;
                rp[mt][1] += tanhf(d.z + b0) * w0 + tanhf(d.w + b1) * w1;
            }
            atomicAdd(&sscore[warpM + mt * 16 + g], rp[mt][0]);
            atomicAdd(&sscore[warpM + mt * 16 + g + 8], rp[mt][1]);
        }
        __syncthreads();
        if (tid < 128) {
            int row = rowBase + tid;
            if (row < n) {
                float sc = sscore[tid];
                score[row] = sc;
                atomicMax(&gmax[batchv[row]], ford(sc));
            }
        }
    } else if (op == 1) {
#pragma unroll
        for (int mt = 0; mt < 2; mt++) {
#pragma unroll
            for (int nt = 0; nt < 8; nt++) {
                int c0 = warpN + nt * 8 + tg * 2;
                int r0 = rowBase + warpM + mt * 16 + g;
                float4 d = acc[mt][nt];
                if (r0 < n)
                    *(__half2*)(Ch + (size_t)r0 * 128 + c0) = __floats2half2_rn(d.x, d.y);
                if (r0 + 8 < n)
                    *(__half2*)(Ch + (size_t)(r0 + 8) * 128 + c0) = __floats2half2_rn(d.z, d.w);
            }
        }
    } else {
#pragma unroll
        for (int mt = 0; mt < 2; mt++) {
#pragma unroll
            for (int nt = 0; nt < 8; nt++) {
                int c0 = warpN + nt * 8 + tg * 2;
                int r0 = rowBase + warpM + mt * 16 + g;
                float4 d = acc[mt][nt];
                if (r0 < n)     *(float2*)(C + (size_t)r0 * 128 + c0) = make_float2(d.x, d.y);
                if (r0 + 8 < n) *(float2*)(C + (size_t)(r0 + 8) * 128 + c0) = make_float2(d.z, d.w);
            }
        }
    }
}

// ---------------------------------------------------------------------------
// GATv2 aggregation: one warp per destination node, online softmax, batch-4.
// xl gathered in fp16 (halves the L2 traffic). GROUP = lanes per head.
// ---------------------------------------------------------------------------
template <int GROUP>
__device__ __forceinline__ float group_reduce(float v) {
    v += __shfl_xor_sync(0xffffffffu, v, 1);
    v += __shfl_xor_sync(0xffffffffu, v, 2);
    if (GROUP == 32) {
        v += __shfl_xor_sync(0xffffffffu, v, 4);
        v += __shfl_xor_sync(0xffffffffu, v, 8);
        v += __shfl_xor_sync(0xffffffffu, v, 16);
    }
    return v;
}

__device__ __forceinline__ float lrelu(float x) { return x > 0.f ? x : x * SLOPE; }

__device__ __forceinline__ float4 load_xl_h(const __half* __restrict__ xlh, int node, int j) {
    float2 raw = *(const float2*)(xlh + (size_t)node * 128 + j);  // 4 halves, 8B LDG
    __half2 h0 = *(__half2*)&raw.x;
    __half2 h1 = *(__half2*)&raw.y;
    float2 f0 = __half22float2(h0);
    float2 f1 = __half22float2(h1);
    return make_float4(f0.x, f0.y, f1.x, f1.y);
}

template <int GROUP>
__global__ __launch_bounds__(256) void gat_agg_kernel(
        const __half* __restrict__ xlh, const float* __restrict__ xr,
        const float* __restrict__ att, const float* __restrict__ bias,
        const float* __restrict__ bn_g, const float* __restrict__ bn_b,
        const float* __restrict__ bn_rm, const float* __restrict__ bn_rv,
        const int* __restrict__ rowstart, const int* __restrict__ csr_src,
        float* __restrict__ out, int n) {
    int w = (blockIdx.x * blockDim.x + threadIdx.x) >> 5;
    if (w >= n) return;
    int lane = threadIdx.x & 31;
    int j = lane * 4;

    float4 r4 = *(const float4*)(xr + (size_t)w * 128 + j);
    float4 a4 = *(const float4*)(att + j);

    int e0 = rowstart[w], e1 = rowstart[w + 1];
    float m = -INFINITY, s = 0.f;
    float4 acc = make_float4(0.f, 0.f, 0.f, 0.f);

    auto score_of = [&](const float4& lv) {
        float sc = lrelu(lv.x + r4.x) * a4.x + lrelu(lv.y + r4.y) * a4.y +
                   lrelu(lv.z + r4.z) * a4.z + lrelu(lv.w + r4.w) * a4.w;
        return group_reduce<GROUP>(sc);
    };

    int e = e0;
#pragma unroll 1
    for (; e + 3 < e1; e += 4) {
        int s0 = csr_src[e + 0], s1 = csr_src[e + 1];
        int s2 = csr_src[e + 2], s3 = csr_src[e + 3];
        float4 l0 = load_xl_h(xlh, s0, j);
        float4 l1 = load_xl_h(xlh, s1, j);
        float4 l2 = load_xl_h(xlh, s2, j);
        float4 l3 = load_xl_h(xlh, s3, j);
        float sc0 = score_of(l0), sc1 = score_of(l1);
        float sc2 = score_of(l2), sc3 = score_of(l3);
        float mn = fmaxf(m, fmaxf(fmaxf(sc0, sc1), fmaxf(sc2, sc3)));
        float scale = __expf(m - mn);
        float p0 = __expf(sc0 - mn), p1 = __expf(sc1 - mn);
        float p2 = __expf(sc2 - mn), p3 = __expf(sc3 - mn);
        s = fmaf(s, scale, p0 + p1 + p2 + p3);
        acc.x = fmaf(acc.x, scale, fmaf(p0, l0.x, fmaf(p1, l1.x, fmaf(p2, l2.x, p3 * l3.x))));
        acc.y = fmaf(acc.y, scale, fmaf(p0, l0.y, fmaf(p1, l1.y, fmaf(p2, l2.y, p3 * l3.y))));
        acc.z = fmaf(acc.z, scale, fmaf(p0, l0.z, fmaf(p1, l1.z, fmaf(p2, l2.z, p3 * l3.z))));
        acc.w = fmaf(acc.w, scale, fmaf(p0, l0.w, fmaf(p1, l1.w, fmaf(p2, l2.w, p3 * l3.w))));
        m = mn;
    }
#pragma unroll 1
    for (; e < e1; e++) {
        int sa = csr_src[e];
        float4 lv = load_xl_h(xlh, sa, j);
        float sc = score_of(lv);
        float mn = fmaxf(m, sc);
        float scale = __expf(m - mn);
        float p = __expf(sc - mn);
        s = fmaf(s, scale, p);
        acc.x = fmaf(acc.x, scale, p * lv.x);
        acc.y = fmaf(acc.y, scale, p * lv.y);
        acc.z = fmaf(acc.z, scale, p * lv.z);
        acc.w = fmaf(acc.w, scale, p * lv.w);
        m = mn;
    }

    float inv = 1.0f / (s + 1e-16f);
    float4 bi = *(const float4*)(bias + j);
    float4 gg = *(const float4*)(bn_g + j);
    float4 bb = *(const float4*)(bn_b + j);
    float4 rm = *(const float4*)(bn_rm + j);
    float4 rv = *(const float4*)(bn_rv + j);

    float4 o;
    o.x = acc.x * inv + bi.x;
    o.y = acc.y * inv + bi.y;
    o.z = acc.z * inv + bi.z;
    o.w = acc.w * inv + bi.w;
    o.x = fmaxf(0.f, (o.x - rm.x) * (gg.x * rsqrtf(rv.x + BN_EPS)) + bb.x);
    o.y = fmaxf(0.f, (o.y - rm.y) * (gg.y * rsqrtf(rv.y + BN_EPS)) + bb.y);
    o.z = fmaxf(0.f, (o.z - rm.z) * (gg.z * rsqrtf(rv.z + BN_EPS)) + bb.z);
    o.w = fmaxf(0.f, (o.w - rm.w) * (gg.w * rsqrtf(rv.w + BN_EPS)) + bb.w);
    *(float4*)(out + (size_t)w * 128 + j) = o;
}

// ---------------------------------------------------------------------------
// Fused exp + weighted pool (unnormalized; fc_head divides by gsum)
// ---------------------------------------------------------------------------
__global__ __launch_bounds__(256) void pool_fused_kernel(
        const float* __restrict__ h2, const float* __restrict__ score,
        const unsigned int* __restrict__ gmax, const int* __restrict__ batch,
        float* __restrict__ gsum, float* __restrict__ pooled, int n) {
    int w = (blockIdx.x * blockDim.x + threadIdx.x) >> 5;
    if (w >= n) return;
    int lane = threadIdx.x & 31;
    int j = lane * 4;
    int g = batch[w];
    float wv = __expf(score[w] - forddec(gmax[g]));
    if (lane == 0) atomicAdd(&gsum[g], wv);
    float4 h = *(const float4*)(h2 + (size_t)w * 128 + j);
    float* base = pooled + (size_t)g * 128 + j;
    atomicAdd(base + 0, wv * h.x);
    atomicAdd(base + 1, wv * h.y);
    atomicAdd(base + 2, wv * h.z);
    atomicAdd(base + 3, wv * h.w);
}

// ---------------------------------------------------------------------------
// fc head: relu((pooled/gsum) @ Wf1 + bf1) @ Wf2 + bf2   -> out[g]
// ---------------------------------------------------------------------------
__global__ __launch_bounds__(128) void fc_head_kernel(
        const float* __restrict__ pooled, const float* __restrict__ gsum,
        const float* __restrict__ Wf1, const float* __restrict__ bf1,
        const float* __restrict__ Wf2, const float* __restrict__ bf2,
        float* __restrict__ out) {
    int g = blockIdx.x;
    int t = threadIdx.x;
    __shared__ float sp[128];
    __shared__ float red[128];
    float inv = 1.0f / (gsum[g] + 1e-16f);
    sp[t] = pooled[(size_t)g * 128 + t] * inv;
    __syncthreads();
    float contrib = 0.f;
    if (t < 100) {
        float acc = bf1[t];
#pragma unroll 8
        for (int k = 0; k < 128; k++) acc = fmaf(sp[k], Wf1[k * 100 + t], acc);
        contrib = fmaxf(acc, 0.f) * Wf2[t];
    }
    red[t] = contrib;
    __syncthreads();
    for (int off = 64; off > 0; off >>= 1) {
        if (t < off) red[t] += red[t + off];
        __syncthreads();
    }
    if (t == 0) out[g] = red[0] + bf2[0];
}

// ---------------------------------------------------------------------------
// Host driver
// ---------------------------------------------------------------------------
extern "C" void kernel_launch(void* const* d_in, const int* in_sizes, int n_in,
                              void* d_out, int out_size) {
    const float* x    = (const float*)d_in[0];
    const int*   ei   = (const int*)d_in[1];
    const int*   batch= (const int*)d_in[2];
    const float* Wl1  = (const float*)d_in[3];
    const float* Wr1  = (const float*)d_in[4];
    const float* att1 = (const float*)d_in[5];
    const float* b1   = (const float*)d_in[6];
    const float* Wl2  = (const float*)d_in[7];
    const float* Wr2  = (const float*)d_in[8];
    const float* att2 = (const float*)d_in[9];
    const float* b2   = (const float*)d_in[10];
    const float* bn_g = (const float*)d_in[11];
    const float* bn_b = (const float*)d_in[12];
    const float* bn_rm= (const float*)d_in[13];
    const float* bn_rv= (const float*)d_in[14];
    const float* Wg1  = (const float*)d_in[15];
    const float* bg1  = (const float*)d_in[16];
    const float* Wg2  = (const float*)d_in[17];
    const float* Wf1  = (const float*)d_in[18];
    const float* bf1  = (const float*)d_in[19];
    const float* Wf2  = (const float*)d_in[20];
    const float* bf2  = (const float*)d_in[21];

    const int n = in_sizes[0] / HID;      // 50000
    const int e = in_sizes[1] / 2;        // 1600000
    const int ng = out_size;              // 500
    const int* src = ei;
    const int* dst = ei + e;

    float *xr, *h1, *h2, *score, *gsum, *pooled;
    __half* xlh;
    int *deg, *cursor, *rowstart, *csr_src, *bsums;
    unsigned int* gmax;
    cudaGetSymbolAddress((void**)&xlh, g_xlh);
    cudaGetSymbolAddress((void**)&xr, g_xr);
    cudaGetSymbolAddress((void**)&h1, g_h1);
    cudaGetSymbolAddress((void**)&h2, g_h2);
    cudaGetSymbolAddress((void**)&deg, g_deg);
    cudaGetSymbolAddress((void**)&cursor, g_cursor);
    cudaGetSymbolAddress((void**)&rowstart, g_rowstart);
    cudaGetSymbolAddress((void**)&bsums, g_bsums);
    cudaGetSymbolAddress((void**)&csr_src, g_csr_src);
    cudaGetSymbolAddress((void**)&score, g_score);
    cudaGetSymbolAddress((void**)&gmax, g_gmax);
    cudaGetSymbolAddress((void**)&gsum, g_gsum);
    cudaGetSymbolAddress((void**)&pooled, g_pooled);

    const int TB = 256;
    int gemmGrid = (n + 127) / 128;
    int warpGrid = (n * 32 + TB - 1) / TB;
    int nScanBlocks = (n + 1023) / 1024;

    // ---- CSR build ----
    cudaMemsetAsync(deg, 0, n * sizeof(int));
    cudaMemsetAsync(cursor, 0, n * sizeof(int));
    count_deg_kernel<<<(e + TB - 1) / TB, TB>>>(dst, deg, e);
    scan_block_kernel<<<nScanBlocks, 1024>>>(deg, rowstart, bsums, n);
    scan_sums_kernel<<<1, 64>>>(bsums, nScanBlocks);
    scan_add_kernel<<<(n + TB - 1) / TB, TB>>>(rowstart, bsums, n);
    fill_csr_kernel<<<(e + TB - 1) / TB, TB>>>(src, dst, rowstart, cursor, csr_src, e);

    // ---- layer 1 ----
    gemm_tf32_kernel<<<gemmGrid, 256>>>(x, Wl1, nullptr, nullptr, xlh,
                                        nullptr, nullptr, nullptr, nullptr, n, 1);
    gemm_tf32_kernel<<<gemmGrid, 256>>>(x, Wr1, nullptr, xr, nullptr,
                                        nullptr, nullptr, nullptr, nullptr, n, 0);
    gat_agg_kernel<4><<<warpGrid, TB>>>(xlh, xr, att1, b1, bn_g, bn_b, bn_rm, bn_rv,
                                        rowstart, csr_src, h1, n);

    // ---- layer 2 ----
    gemm_tf32_kernel<<<gemmGrid, 256>>>(h1, Wl2, nullptr, nullptr, xlh,
                                        nullptr, nullptr, nullptr, nullptr, n, 1);
    gemm_tf32_kernel<<<gemmGrid, 256>>>(h1, Wr2, nullptr, xr, nullptr,
                                        nullptr, nullptr, nullptr, nullptr, n, 0);
    gat_agg_kernel<32><<<warpGrid, TB>>>(xlh, xr, att2, b2, bn_g, bn_b, bn_rm, bn_rv,
                                         rowstart, csr_src, h2, n);

    // ---- attentional aggregation (gate fused into GEMM epilogue) ----
    cudaMemsetAsync(gmax, 0, ng * sizeof(unsigned int));
    cudaMemsetAsync(gsum, 0, ng * sizeof(float));
    cudaMemsetAsync(pooled, 0, ng * HID * sizeof(float));
    gemm_tf32_kernel<<<gemmGrid, 256>>>(h2, Wg1, bg1, nullptr, nullptr,
                                        batch, Wg2, gmax, score, n, 2);
    pool_fused_kernel<<<warpGrid, TB>>>(h2, score, gmax, batch, gsum, pooled, n);

    // ---- fc head ----
    fc_head_kernel<<<ng, 128>>>(pooled, gsum, Wf1, bf1, Wf2, bf2, (float*)d_out);
}